// round 2
// baseline (speedup 1.0000x reference)
#include <cuda_runtime.h>

#define Bq  2
#define Sq  2048
#define Dq  1024
#define Hq  16
#define DKV 64

// ---------------- scratch (static device arrays; no cudaMalloc) -------------
__device__ float g_Q[Bq * Hq * Sq * DKV];      // [b,h,s,dkv]
__device__ float g_K[Bq * Hq * Sq * DKV];
__device__ float g_V[Bq * Hq * Sq * DKV];
__device__ float g_ctx[Bq * Sq * Dq];          // [b,s,d]
__device__ float g_rowsum[Bq * Hq * Sq];
__device__ float g_bias[Hq * 4096];            // [h][delta], delta = k-q+2048

// ---------------- fast exp in the FMA pipe ----------------------------------
__device__ __forceinline__ float fexp(float x) {
    float t = x * 1.4426950408889634f;
    t = fmaxf(t, -126.0f);
    float nf = floorf(t);
    float u = (t - nf) * 0.6931471805599453f;    // [0, ln2)
    float p = fmaf(u, 1.0f / 720.0f, 1.0f / 120.0f);
    p = fmaf(p, u, 1.0f / 24.0f);
    p = fmaf(p, u, 1.0f / 6.0f);
    p = fmaf(p, u, 0.5f);
    p = fmaf(p, u, 1.0f);
    p = fmaf(p, u, 1.0f);
    int ei = (int)nf;
    return p * __int_as_float((ei + 127) << 23);
}

// ---------------- T5 relative-position bias table ---------------------------
__global__ void bias_init(const float* __restrict__ rel_bias) {
    int d = blockIdx.x * 256 + threadIdx.x;
    if (d >= 4096) return;
    int n = -(d - 2048);
    int ret = 0;
    if (n < 0) { ret = 16; n = -n; }
    int bucket;
    if      (n <  8) bucket = n;
    else if (n < 12) bucket = 8;
    else if (n < 16) bucket = 9;
    else if (n < 23) bucket = 10;
    else if (n < 32) bucket = 11;
    else if (n < 46) bucket = 12;
    else if (n < 64) bucket = 13;
    else if (n < 91) bucket = 14;
    else             bucket = 15;
    bucket += ret;
    #pragma unroll
    for (int h = 0; h < Hq; h++)
        g_bias[h * 4096 + d] = rel_bias[bucket * Hq + h];
}

// ---------------- 4096x1024 @ 1024x1024 GEMM: 128x128 tile, 8x8 micro -------
__global__ __launch_bounds__(256, 2) void gemm4096(
    const float* __restrict__ Xin, const float* __restrict__ W,
    float* __restrict__ Yrm, int mode)
{
    __shared__ float Xs[16][132];   // [k][m] transposed
    __shared__ float Ws[16][132];   // [k][n]
    const float* X = (mode == 3) ? g_ctx : Xin;
    const int m0 = blockIdx.y << 7;
    const int n0 = blockIdx.x << 7;
    const int t = threadIdx.x;
    const int tx = t & 15, ty = t >> 4;
    const int xr = t >> 2, xc = (t & 3) << 2;   // X: 64 rows x 16 cols per pass
    const int wr = t >> 4, wc = (t & 15) << 2;  // W: 16 rows x 64 cols per pass

    float4 xv0 = *(const float4*)&X[(m0 + xr) * Dq + xc];
    float4 xv1 = *(const float4*)&X[(m0 + 64 + xr) * Dq + xc];
    float4 wv0 = *(const float4*)&W[wr * Dq + n0 + wc];
    float4 wv1 = *(const float4*)&W[wr * Dq + n0 + 64 + wc];

    float acc[8][8] = {};
    for (int k0 = 0; k0 < Dq; k0 += 16) {
        __syncthreads();
        Xs[xc + 0][xr] = xv0.x; Xs[xc + 1][xr] = xv0.y;
        Xs[xc + 2][xr] = xv0.z; Xs[xc + 3][xr] = xv0.w;
        Xs[xc + 0][64 + xr] = xv1.x; Xs[xc + 1][64 + xr] = xv1.y;
        Xs[xc + 2][64 + xr] = xv1.z; Xs[xc + 3][64 + xr] = xv1.w;
        *(float4*)&Ws[wr][wc] = wv0;
        *(float4*)&Ws[wr][64 + wc] = wv1;
        __syncthreads();
        if (k0 + 16 < Dq) {                      // prefetch next slab
            xv0 = *(const float4*)&X[(m0 + xr) * Dq + k0 + 16 + xc];
            xv1 = *(const float4*)&X[(m0 + 64 + xr) * Dq + k0 + 16 + xc];
            wv0 = *(const float4*)&W[(k0 + 16 + wr) * Dq + n0 + wc];
            wv1 = *(const float4*)&W[(k0 + 16 + wr) * Dq + n0 + 64 + wc];
        }
        #pragma unroll
        for (int kk = 0; kk < 16; kk++) {
            float4 a0 = *(const float4*)&Xs[kk][ty << 2];
            float4 a1 = *(const float4*)&Xs[kk][64 + (ty << 2)];
            float4 b0 = *(const float4*)&Ws[kk][tx << 2];
            float4 b1 = *(const float4*)&Ws[kk][64 + (tx << 2)];
            float a[8] = {a0.x, a0.y, a0.z, a0.w, a1.x, a1.y, a1.z, a1.w};
            float bb[8] = {b0.x, b0.y, b0.z, b0.w, b1.x, b1.y, b1.z, b1.w};
            #pragma unroll
            for (int r = 0; r < 8; r++)
                #pragma unroll
                for (int c = 0; c < 8; c++)
                    acc[r][c] = fmaf(a[r], bb[c], acc[r][c]);
        }
    }

    if (mode <= 2) {
        float* dst = (mode == 0) ? g_Q : (mode == 1) ? g_K : g_V;
        const int h0 = n0 >> 6;                  // group0 head, group1 = h0+1
        const int dv = tx << 2;
        #pragma unroll
        for (int r = 0; r < 8; r++) {
            int m = m0 + ((r < 4) ? (ty << 2) + r : 64 + (ty << 2) + r - 4);
            int b = m >> 11, s = m & 2047;
            *(float4*)&dst[((b * Hq + h0) * Sq + s) * DKV + dv] =
                make_float4(acc[r][0], acc[r][1], acc[r][2], acc[r][3]);
            *(float4*)&dst[((b * Hq + h0 + 1) * Sq + s) * DKV + dv] =
                make_float4(acc[r][4], acc[r][5], acc[r][6], acc[r][7]);
        }
    } else {
        #pragma unroll
        for (int r = 0; r < 8; r++) {
            int m = m0 + ((r < 4) ? (ty << 2) + r : 64 + (ty << 2) + r - 4);
            *(float4*)&Yrm[m * Dq + n0 + (tx << 2)] =
                make_float4(acc[r][0], acc[r][1], acc[r][2], acc[r][3]);
            *(float4*)&Yrm[m * Dq + n0 + 64 + (tx << 2)] =
                make_float4(acc[r][4], acc[r][5], acc[r][6], acc[r][7]);
        }
    }
}

// ---------------- scores: store exp(QK/8 + bias) (masked->0) + row sums -----
__global__ __launch_bounds__(256, 2) void attn_scores(
    const int* __restrict__ mask, float* __restrict__ attn)
{
    __shared__ float Qs[64][132];   // [dkv][q]
    __shared__ float Ks[64][132];   // [dkv][k]
    __shared__ float biasW[256];
    __shared__ int   maskS[128];
    const int q0 = blockIdx.x << 7;
    const int h = blockIdx.y, b = blockIdx.z;
    const int bh = b * Hq + h;
    const int t = threadIdx.x;
    const int tx = t & 15, ty = t >> 4;

    #pragma unroll
    for (int p = 0; p < 8; p++) {                // Q tile once, transposed
        int idx = t + (p << 8);
        int row = idx >> 4, c4 = (idx & 15) << 2;
        float4 v = *(const float4*)&g_Q[(bh * Sq + q0 + row) * DKV + c4];
        Qs[c4 + 0][row] = v.x; Qs[c4 + 1][row] = v.y;
        Qs[c4 + 2][row] = v.z; Qs[c4 + 3][row] = v.w;
    }
    float rsum[8] = {};
    for (int k0 = 0; k0 < Sq; k0 += 128) {
        __syncthreads();
        #pragma unroll
        for (int p = 0; p < 8; p++) {            // K tile, transposed
            int idx = t + (p << 8);
            int row = idx >> 4, c4 = (idx & 15) << 2;
            float4 v = *(const float4*)&g_K[(bh * Sq + k0 + row) * DKV + c4];
            Ks[c4 + 0][row] = v.x; Ks[c4 + 1][row] = v.y;
            Ks[c4 + 2][row] = v.z; Ks[c4 + 3][row] = v.w;
        }
        if (t < 255) biasW[t] = g_bias[h * 4096 + (k0 - q0 + t - 127 + 2048)];
        if (t < 128) maskS[t] = mask[b * Sq + k0 + t];
        __syncthreads();

        float acc[8][8] = {};
        #pragma unroll 8
        for (int kk = 0; kk < 64; kk++) {
            float4 a0 = *(const float4*)&Qs[kk][ty << 2];
            float4 a1 = *(const float4*)&Qs[kk][64 + (ty << 2)];
            float4 b0 = *(const float4*)&Ks[kk][tx << 2];
            float4 b1 = *(const float4*)&Ks[kk][64 + (tx << 2)];
            float a[8] = {a0.x, a0.y, a0.z, a0.w, a1.x, a1.y, a1.z, a1.w};
            float bb[8] = {b0.x, b0.y, b0.z, b0.w, b1.x, b1.y, b1.z, b1.w};
            #pragma unroll
            for (int r = 0; r < 8; r++)
                #pragma unroll
                for (int c = 0; c < 8; c++)
                    acc[r][c] = fmaf(a[r], bb[c], acc[r][c]);
        }
        #pragma unroll
        for (int r = 0; r < 8; r++) {
            int qr = (r < 4) ? (ty << 2) + r : 64 + (ty << 2) + r - 4;
            #pragma unroll
            for (int g = 0; g < 2; g++) {
                int kc0 = (g << 6) + (tx << 2);
                float4 e;
                float* ep = &e.x;
                #pragma unroll
                for (int c = 0; c < 4; c++) {
                    int kc = kc0 + c;
                    float sc = fmaf(acc[r][(g << 2) + c], 0.125f, biasW[kc - qr + 127]);
                    float ee = (maskS[kc] == 0) ? 0.0f : fexp(sc);
                    ep[c] = ee;
                    rsum[r] += ee;
                }
                *(float4*)&attn[(size_t)(bh * Sq + q0 + qr) * Sq + k0 + kc0] = e;
            }
        }
    }
    #pragma unroll
    for (int r = 0; r < 8; r++) {
        float e = rsum[r];
        e += __shfl_xor_sync(0xffffffffu, e, 8, 16);
        e += __shfl_xor_sync(0xffffffffu, e, 4, 16);
        e += __shfl_xor_sync(0xffffffffu, e, 2, 16);
        e += __shfl_xor_sync(0xffffffffu, e, 1, 16);
        if (tx == 0) {
            int qr = (r < 4) ? (ty << 2) + r : 64 + (ty << 2) + r - 4;
            g_rowsum[bh * Sq + q0 + qr] = e;
        }
    }
}

// ---------------- context: P = e/l written in place; ctx = P @ V ------------
__global__ __launch_bounds__(128) void attn_ctx(float* __restrict__ attn)
{
    __shared__ float Ps[64][132];   // [k][q]
    __shared__ float Vs[64][68];    // [k][dv]
    __shared__ float rinv[128];
    const int q0 = blockIdx.x << 7;
    const int h = blockIdx.y, b = blockIdx.z;
    const int bh = b * Hq + h;
    const int t = threadIdx.x;
    const int tx = t & 7, ty = t >> 3;
    rinv[t] = 1.0f / g_rowsum[bh * Sq + q0 + t];

    float acc[8][8] = {};
    for (int k0 = 0; k0 < Sq; k0 += 64) {
        __syncthreads();
        #pragma unroll
        for (int p = 0; p < 16; p++) {           // P tile: normalize + writeback
            int idx = t + (p << 7);
            int row = idx >> 4, c4 = (idx & 15) << 2;
            size_t gi = (size_t)(bh * Sq + q0 + row) * Sq + k0 + c4;
            float4 v = *(const float4*)&attn[gi];
            float ri = rinv[row];
            v.x *= ri; v.y *= ri; v.z *= ri; v.w *= ri;
            *(float4*)&attn[gi] = v;             // final attn_weights output
            Ps[c4 + 0][row] = v.x; Ps[c4 + 1][row] = v.y;
            Ps[c4 + 2][row] = v.z; Ps[c4 + 3][row] = v.w;
        }
        #pragma unroll
        for (int p = 0; p < 8; p++) {            // V tile
            int idx = t + (p << 7);
            int row = idx >> 4, c4 = (idx & 15) << 2;
            *(float4*)&Vs[row][c4] =
                *(const float4*)&g_V[(bh * Sq + k0 + row) * DKV + c4];
        }
        __syncthreads();
        #pragma unroll 8
        for (int kk = 0; kk < 64; kk++) {
            float4 a0 = *(const float4*)&Ps[kk][ty << 2];
            float4 a1 = *(const float4*)&Ps[kk][64 + (ty << 2)];
            float4 b0 = *(const float4*)&Vs[kk][tx << 2];
            float4 b1 = *(const float4*)&Vs[kk][32 + (tx << 2)];
            float a[8] = {a0.x, a0.y, a0.z, a0.w, a1.x, a1.y, a1.z, a1.w};
            float bb[8] = {b0.x, b0.y, b0.z, b0.w, b1.x, b1.y, b1.z, b1.w};
            #pragma unroll
            for (int r = 0; r < 8; r++)
                #pragma unroll
                for (int c = 0; c < 8; c++)
                    acc[r][c] = fmaf(a[r], bb[c], acc[r][c]);
        }
    }
    #pragma unroll
    for (int r = 0; r < 8; r++) {
        int q = q0 + ((r < 4) ? (ty << 2) + r : 64 + (ty << 2) + r - 4);
        *(float4*)&g_ctx[(b * Sq + q) * Dq + (h << 6) + (tx << 2)] =
            make_float4(acc[r][0], acc[r][1], acc[r][2], acc[r][3]);
        *(float4*)&g_ctx[(b * Sq + q) * Dq + (h << 6) + 32 + (tx << 2)] =
            make_float4(acc[r][4], acc[r][5], acc[r][6], acc[r][7]);
    }
}

// ---------------- launch -----------------------------------------------------
extern "C" void kernel_launch(void* const* d_in, const int* in_sizes, int n_in,
                              void* d_out, int out_size)
{
    const float* hs   = (const float*)d_in[0];
    const int*   mask = (const int*)d_in[1];
    const float* Wq   = (const float*)d_in[2];
    const float* Wk   = (const float*)d_in[3];
    const float* Wv   = (const float*)d_in[4];
    const float* Wo   = (const float*)d_in[5];
    const float* rb   = (const float*)d_in[6];
    float* out  = (float*)d_out;                           // [2,2048,1024]
    float* attn = out + (size_t)Bq * Sq * Dq;              // [2,16,2048,2048]

    bias_init<<<16, 256>>>(rb);

    dim3 gp(Dq / 128, (Bq * Sq) / 128);          // (8, 32)
    gemm4096<<<gp, 256>>>(hs, Wq, nullptr, 0);
    gemm4096<<<gp, 256>>>(hs, Wk, nullptr, 1);
    gemm4096<<<gp, 256>>>(hs, Wv, nullptr, 2);

    dim3 ga(Sq / 128, Hq, Bq);                   // (16, 16, 2)
    attn_scores<<<ga, 256>>>(mask, attn);
    attn_ctx<<<ga, 128>>>(attn);

    gemm4096<<<gp, 256>>>(nullptr, Wo, out, 3);
}